// round 4
// baseline (speedup 1.0000x reference)
#include <cuda_runtime.h>
#include <cuda_bf16.h>
#include <math.h>

// ---------------- problem constants ----------------
#define VOCAB 50257
#define EMBD  32
#define HID   8
#define NB    48     // batch
#define NT    128    // seq
#define NROWS (NB*NT)          // 6144
#define VP    51200            // padded vocab width (400 chunks of 128)
#define NCH   400              // chunks of 128 cols
#define VS    16               // vocab splits
#define CPC   (NCH/VS)         // 25 chunks per CTA

// ---------------- device scratch (no cudaMalloc allowed) ----------------
__device__ __align__(16) float g_W4[4 * 16 * VP];   // 4 shifted copies of h2o, padded
__device__ __align__(16) float g_Bs[NB * VP];       // per-b shifted bias, padded with -1e30
__device__ __align__(16) float g_E [NB * NT * HID]; // E[b][t][j] = emb @ i2h[:32]
__device__ __align__(16) float g_H [NB * NT * 16];  // H[b][t][0:8]=hf_used, [8:16]=hb_used
__device__ float g_Zpart[NROWS * VS];
__device__ float g_LZ  [NROWS];

typedef unsigned long long u64;

// ---------------- f32x2 helpers (sm_103a packed fp32) ----------------
__device__ __forceinline__ u64 pk2(float x) {
    u64 r; asm("mov.b64 %0,{%1,%1};" : "=l"(r) : "f"(x)); return r;
}
__device__ __forceinline__ u64 f2fma(u64 a, u64 b, u64 c) {
    u64 d; asm("fma.rn.f32x2 %0,%1,%2,%3;" : "=l"(d) : "l"(a), "l"(b), "l"(c)); return d;
}
__device__ __forceinline__ u64 f2add(u64 a, u64 b) {
    u64 d; asm("add.rn.f32x2 %0,%1,%2;" : "=l"(d) : "l"(a), "l"(b)); return d;
}
__device__ __forceinline__ float2 up2(u64 a) {
    float2 f; asm("mov.b64 {%0,%1},%2;" : "=f"(f.x), "=f"(f.y) : "l"(a)); return f;
}

// ---------------- prep: build shifted/padded W copies ----------------
__global__ void prep_w_kernel(const float* __restrict__ h2o) {
    int idx = blockIdx.x * blockDim.x + threadIdx.x;
    int total = 4 * 16 * VP;
    if (idx >= total) return;
    int s = idx / (16 * VP);
    int rem = idx - s * (16 * VP);
    int k = rem / VP;
    int i = rem - k * VP;
    int lo = i - s;
    float v = 0.0f;
    if (lo >= 0 && lo < VOCAB) v = h2o[k * VOCAB + lo];
    g_W4[idx] = v;
}

__global__ void prep_b_kernel(const float* __restrict__ bias) {
    int idx = blockIdx.x * blockDim.x + threadIdx.x;
    int total = NB * VP;
    if (idx >= total) return;
    int b = idx / VP;
    int i = idx - b * VP;
    int s = b & 3;
    int lo = i - s;
    float v = -1e30f;
    if (lo >= 0 && lo < VOCAB) v = bias[b * VOCAB + lo];
    g_Bs[idx] = v;
}

// ---------------- E = gather(we, ids) @ i2h[0:32,:] ----------------
__global__ void emb_kernel(const int* __restrict__ ids,
                           const float* __restrict__ we,
                           const float* __restrict__ i2h) {
    int gid = blockIdx.x * blockDim.x + threadIdx.x;  // 6144*8 threads
    if (gid >= NROWS * HID) return;
    int r = gid >> 3;          // row in (t,b) order
    int j = gid & 7;
    int t = r / NB;
    int b = r - t * NB;
    int id = ids[r];
    const float* wr = we + (long)id * EMBD;
    float acc = 0.0f;
#pragma unroll
    for (int k = 0; k < EMBD; k++)
        acc += __ldg(wr + k) * __ldg(i2h + k * HID + j);
    g_E[((b << 7) + t) * HID + j] = acc;
}

// ---------------- RNN scans: 96 warps (48 b x 2 dir) ----------------
__global__ void rnn_kernel(const float* __restrict__ i2h,
                           const float* __restrict__ h0f,
                           const float* __restrict__ h0b) {
    int wg = blockIdx.x * (blockDim.x >> 5) + (threadIdx.x >> 5);  // 0..95
    if (wg >= 2 * NB) return;
    int lane = threadIdx.x & 31;
    int j = lane & 7;
    int dir = (wg >= NB) ? 1 : 0;
    int b = wg - dir * NB;

    float U[HID];
#pragma unroll
    for (int kk = 0; kk < HID; kk++)
        U[kk] = i2h[(EMBD + kk) * HID + j];

    float h = dir ? h0b[b * HID + j] : h0f[b * HID + j];

    for (int step = 0; step < NT; step++) {
        int t = dir ? (NT - 1 - step) : step;
        if (lane < HID)
            g_H[((b << 7) + t) * 16 + dir * HID + j] = h;  // state BEFORE consuming emb[t]
        float acc = g_E[((b << 7) + t) * HID + j];
#pragma unroll
        for (int kk = 0; kk < HID; kk++)
            acc += __shfl_sync(0xFFFFFFFFu, h, kk) * U[kk];
        h = tanhf(acc);
    }
}

// ---------------- main passes ----------------
// grid: 48*4*16 = 3072 CTAs, 256 threads.
// CTA = (b, 32-t tile, vocab split). Warp owns 4 rows; lane owns 4 cols/chunk.
template<int PASS>
__global__ __launch_bounds__(256, 2) void pass_kernel(float* __restrict__ out) {
    int bx = blockIdx.x;
    int vs = bx & (VS - 1);
    int tmp = bx >> 4;
    int tt = tmp & 3;
    int b = tmp >> 2;
    int t0 = tt << 5;
    int s = b & 3;

    const float* __restrict__ W  = g_W4 + s * (16 * VP);
    const float* __restrict__ Bp = g_Bs + b * VP;

    __shared__ __align__(16) u64 smh[32 * 16];   // (h,h) packed per row,k
    __shared__ u64 smlz[32];                     // (-lz,-lz) packed

    int tid = threadIdx.x;
    for (int i = tid; i < 512; i += 256) {
        int r = i >> 4, k = i & 15;
        float v = g_H[((b << 7) + t0 + r) * 16 + k];
        smh[i] = pk2(v);
    }
    if (PASS == 2 && tid < 32) {
        float lz = g_LZ[(b << 7) + t0 + tid];
        smlz[tid] = pk2(-lz);
    }
    __syncthreads();

    int warp = tid >> 5, lane = tid & 31;
    int r0 = warp << 2;
    float z0 = 0.f, z1 = 0.f, z2 = 0.f, z3 = 0.f;

    for (int ci = 0; ci < CPC; ci++) {
        int col = ((ci << 4) + vs) * 128 + (lane << 2);
        u64 wA[16], wB[16];
#pragma unroll
        for (int k = 0; k < 16; k++) {
            ulonglong2 wk = *(const ulonglong2*)(W + k * VP + col);
            wA[k] = wk.x; wB[k] = wk.y;
        }
        ulonglong2 bb = *(const ulonglong2*)(Bp + col);

#pragma unroll
        for (int r = 0; r < 4; r++) {
            int row = r0 + r;
            u64 a0 = bb.x, a1 = bb.y;
            const ulonglong2* hp2 = (const ulonglong2*)&smh[row << 4];
#pragma unroll
            for (int k2 = 0; k2 < 8; k2++) {
                ulonglong2 hh = hp2[k2];
                a0 = f2fma(hh.x, wA[2 * k2],     a0);
                a1 = f2fma(hh.x, wB[2 * k2],     a1);
                a0 = f2fma(hh.y, wA[2 * k2 + 1], a0);
                a1 = f2fma(hh.y, wB[2 * k2 + 1], a1);
            }
            if (PASS == 1) {
                float2 p = up2(a0), q = up2(a1);
                float e = (__expf(p.x) + __expf(p.y)) + (__expf(q.x) + __expf(q.y));
                if (r == 0) z0 += e; else if (r == 1) z1 += e;
                else if (r == 2) z2 += e; else z3 += e;
            } else {
                a0 = f2add(a0, smlz[row]);
                a1 = f2add(a1, smlz[row]);
                int t = t0 + row;
                long rowbase = (long)(t * NB + b) * VOCAB;
                int lo = col - s;
                float2 p = up2(a0), q = up2(a1);
                if (lo >= 0 && lo + 4 <= VOCAB) {
                    float4 v4 = make_float4(p.x, p.y, q.x, q.y);
                    __stcs((float4*)(out + rowbase + lo), v4);
                } else {
                    float vals[4] = {p.x, p.y, q.x, q.y};
#pragma unroll
                    for (int e = 0; e < 4; e++) {
                        int v = lo + e;
                        if (v >= 0 && v < VOCAB) __stcs(out + rowbase + v, vals[e]);
                    }
                }
            }
        }
    }

    if (PASS == 1) {
        float zz[4] = {z0, z1, z2, z3};
#pragma unroll
        for (int r = 0; r < 4; r++) {
            float zr = zz[r];
#pragma unroll
            for (int o = 16; o; o >>= 1) zr += __shfl_xor_sync(0xFFFFFFFFu, zr, o);
            if (lane == 0)
                g_Zpart[((b << 7) + t0 + r0 + r) * VS + vs] = zr;
        }
    }
}

// ---------------- reduce Z partials -> logZ ----------------
__global__ void reduce_kernel() {
    int r = blockIdx.x * blockDim.x + threadIdx.x;
    if (r >= NROWS) return;
    float ssum = 0.0f;
#pragma unroll
    for (int v = 0; v < VS; v++) ssum += g_Zpart[r * VS + v];
    g_LZ[r] = logf(ssum);
}

// ---------------- launch ----------------
extern "C" void kernel_launch(void* const* d_in, const int* in_sizes, int n_in,
                              void* d_out, int out_size) {
    const int*   ids  = (const int*)  d_in[0];
    const float* we   = (const float*)d_in[1];
    const float* i2h  = (const float*)d_in[2];
    const float* h2o  = (const float*)d_in[3];
    const float* bias = (const float*)d_in[4];
    const float* h0f  = (const float*)d_in[5];
    const float* h0b  = (const float*)d_in[6];
    float* out = (float*)d_out;

    {
        int n = 4 * 16 * VP;
        prep_w_kernel<<<(n + 255) / 256, 256>>>(h2o);
    }
    {
        int n = NB * VP;
        prep_b_kernel<<<(n + 255) / 256, 256>>>(bias);
    }
    {
        int n = NROWS * HID;
        emb_kernel<<<(n + 255) / 256, 256>>>(ids, we, i2h);
    }
    rnn_kernel<<<24, 128>>>(i2h, h0f, h0b);

    pass_kernel<1><<<NB * 4 * VS, 256>>>(out);
    reduce_kernel<<<(NROWS + 255) / 256, 256>>>();
    pass_kernel<2><<<NB * 4 * VS, 256>>>(out);
}